// round 6
// baseline (speedup 1.0000x reference)
#include <cuda_runtime.h>
#include <cuda_bf16.h>
#include <math.h>

#define BN     8192
#define ZD     128
#define NC     62
#define NP     93
#define P2     96        // padded proxies
#define NA     2730      // anchors 0,3,...,8187
#define EPSV   1e-6f
#define EPS2T  1.28e-10f // ZD*EPS^2
#define SZP    132       // padded smem z row (floats)
#define NBLK   129       // 128 tile blocks + 1 service block  (< 148 SMs!)
#define NTHR   384
#define NWARPS_TOT (NBLK * 12)   // 1548

// ---------------- persistent scratch (device globals, zero-init) -------------
__device__ float g_prxT[ZD * P2];      // [k][p], cols 93..95 remain 0
__device__ float g_pss[P2];
__device__ float g_psum[P2];
__device__ int   g_yrel[BN];
__device__ int   g_start[NC + 1];
__device__ int   g_clsidx[BN];
__device__ float g_Dpz[P2 * BN];       // dist(proxy p, z j), eps sign psum-zs
__device__ float g_DT [BN * P2];       // dist(z j, proxy p), eps sign zs-psum
__device__ float g_loss[NA];
__device__ unsigned int g_done;
__device__ unsigned int g_bar_cnt;
__device__ volatile unsigned int g_bar_gen;   // monotonically increasing

// ---------------- helpers ---------------------------------------------------
__device__ __forceinline__ float warp_sum(float v) {
#pragma unroll
    for (int o = 16; o; o >>= 1) v += __shfl_xor_sync(0xffffffffu, v, o);
    return v;
}
__device__ __forceinline__ void warp_argmin(float& v, int& i) {
#pragma unroll
    for (int o = 16; o; o >>= 1) {
        float v2 = __shfl_xor_sync(0xffffffffu, v, o);
        int   i2 = __shfl_xor_sync(0xffffffffu, i, o);
        if (v2 < v || (v2 == v && i2 < i)) { v = v2; i = i2; }
    }
}
__device__ __forceinline__ void warp_argmax(float& v, int& i) {
#pragma unroll
    for (int o = 16; o; o >>= 1) {
        float v2 = __shfl_xor_sync(0xffffffffu, v, o);
        int   i2 = __shfl_xor_sync(0xffffffffu, i, o);
        if (v2 > v || (v2 == v && i2 < i)) { v = v2; i = i2; }
    }
}

// software grid barrier — safe: all NBLK CTAs co-resident (NBLK < #SMs)
__device__ __forceinline__ void grid_sync() {
    __syncthreads();
    if (threadIdx.x == 0) {
        __threadfence();
        unsigned gen = g_bar_gen;                 // read BEFORE arriving
        if (atomicAdd(&g_bar_cnt, 1u) == NBLK - 1) {
            g_bar_cnt = 0;
            __threadfence();
            g_bar_gen = gen + 1;
        } else {
            while (g_bar_gen == gen) { }
        }
        __threadfence();
    }
    __syncthreads();
}

// ============================ THE kernel =====================================
__global__ void __launch_bounds__(NTHR) k_all(const float* __restrict__ z,
                                              const int* __restrict__ y_idx,
                                              const int* __restrict__ y_map,
                                              const float* __restrict__ proxies,
                                              float* __restrict__ out) {
    __shared__ float s_z[64 * SZP];      // ~33.8 KB (tile blocks only)
    __shared__ float s_zz[64], s_zs[64];
    __shared__ int   s_inv[NC];
    __shared__ int   s_cnt[NC], s_cur[NC], s_start[NC + 1];
    __shared__ float rbuf[12];
    __shared__ int   s_last;

    int b = blockIdx.x, t = threadIdx.x;
    int w = t >> 5, lane = t & 31;

    // ---------------- Phase A (overlapped, pre-barrier) ----------------------
    if (b < 128) {
        // stage 64 z rows; stride 384 warp-aligned -> free per-row stats
        const float4* z4 = (const float4*)z;
        for (int idx = t; idx < 64 * 32; idx += NTHR) {
            int r = idx >> 5, q = idx & 31;      // r warp-uniform
            float4 v = z4[(size_t)(b * 64 + r) * 32 + q];
            float* dst = &s_z[r * SZP + 4 * q];
            dst[0] = v.x; dst[1] = v.y; dst[2] = v.z; dst[3] = v.w;
            float s  = (v.x + v.y) + (v.z + v.w);
            float ss = (v.x * v.x + v.y * v.y) + (v.z * v.z + v.w * v.w);
#pragma unroll
            for (int o = 16; o; o >>= 1) {
                s  += __shfl_xor_sync(0xffffffffu, s, o);
                ss += __shfl_xor_sync(0xffffffffu, ss, o);
            }
            if (lane == 0) { s_zs[r] = s; s_zz[r] = ss; }
        }
        // y_rel for this block's 64 rows (inverse map)
        if (t < NC) s_inv[y_map[t]] = t;
        __syncthreads();
        if (t < 64) {
            int row = b * 64 + t;
            g_yrel[row] = s_inv[y_idx[row]];
        }
    } else {
        // service block: normalize proxies -> prxT + psum/pss
        for (int p = w; p < NP; p += 12) {
            float4 v = ((const float4*)(proxies + p * ZD))[lane];
            float ss = warp_sum(v.x * v.x + v.y * v.y + v.z * v.z + v.w * v.w);
            float inv = 1.f / fmaxf(sqrtf(ss), 1e-12f);
            float4 o = make_float4(v.x * inv, v.y * inv, v.z * inv, v.w * inv);
            int k0 = 4 * lane;
            g_prxT[(k0 + 0) * P2 + p] = o.x;
            g_prxT[(k0 + 1) * P2 + p] = o.y;
            g_prxT[(k0 + 2) * P2 + p] = o.z;
            g_prxT[(k0 + 3) * P2 + p] = o.w;
            float so  = warp_sum(o.x + o.y + o.z + o.w);
            float so2 = warp_sum(o.x * o.x + o.y * o.y + o.z * o.z + o.w * o.w);
            if (lane == 0) { g_psum[p] = so; g_pss[p] = so2; }
        }
    }

    grid_sync();   // prxT + yrel ready

    // ---------------- Phase B: dist tiles (0..127) | scatter (128) -----------
    if (b < 128) {
        int pg = t % 24, sg = t / 24;        // 24 proxy-groups x 16 sample-groups
        int p0 = 4 * pg, s0 = 4 * sg;
        const float4* prxT4 = (const float4*)g_prxT;

        float acc[4][4];
#pragma unroll
        for (int j = 0; j < 4; j++)
#pragma unroll
            for (int i = 0; i < 4; i++) acc[j][i] = 0.f;

#pragma unroll 4
        for (int k = 0; k < ZD; k++) {
            float4 pv = prxT4[k * 24 + pg];
            float zv0 = s_z[(s0 + 0) * SZP + k];
            float zv1 = s_z[(s0 + 1) * SZP + k];
            float zv2 = s_z[(s0 + 2) * SZP + k];
            float zv3 = s_z[(s0 + 3) * SZP + k];
            acc[0][0] = fmaf(pv.x, zv0, acc[0][0]); acc[0][1] = fmaf(pv.x, zv1, acc[0][1]);
            acc[0][2] = fmaf(pv.x, zv2, acc[0][2]); acc[0][3] = fmaf(pv.x, zv3, acc[0][3]);
            acc[1][0] = fmaf(pv.y, zv0, acc[1][0]); acc[1][1] = fmaf(pv.y, zv1, acc[1][1]);
            acc[1][2] = fmaf(pv.y, zv2, acc[1][2]); acc[1][3] = fmaf(pv.y, zv3, acc[1][3]);
            acc[2][0] = fmaf(pv.z, zv0, acc[2][0]); acc[2][1] = fmaf(pv.z, zv1, acc[2][1]);
            acc[2][2] = fmaf(pv.z, zv2, acc[2][2]); acc[2][3] = fmaf(pv.z, zv3, acc[2][3]);
            acc[3][0] = fmaf(pv.w, zv0, acc[3][0]); acc[3][1] = fmaf(pv.w, zv1, acc[3][1]);
            acc[3][2] = fmaf(pv.w, zv2, acc[3][2]); acc[3][3] = fmaf(pv.w, zv3, acc[3][3]);
        }

        int sBase = b * 64 + s0;
        float pssv[4], psmv[4], zzv[4], zsv[4];
#pragma unroll
        for (int j = 0; j < 4; j++) { pssv[j] = g_pss[p0 + j]; psmv[j] = g_psum[p0 + j]; }
#pragma unroll
        for (int i = 0; i < 4; i++) { zzv[i] = s_zz[s0 + i]; zsv[i] = s_zs[s0 + i]; }

        float dpz[4][4], dzp[4][4];
#pragma unroll
        for (int j = 0; j < 4; j++)
#pragma unroll
            for (int i = 0; i < 4; i++) {
                float base = zzv[i] + pssv[j] - 2.f * acc[j][i];
                float e = 2.f * EPSV * (psmv[j] - zsv[i]);
                dpz[j][i] = sqrtf(fmaxf(base + e + EPS2T, 0.f));
                dzp[j][i] = sqrtf(fmaxf(base - e + EPS2T, 0.f));
            }

#pragma unroll
        for (int j = 0; j < 4; j++)
            *(float4*)(g_Dpz + (size_t)(p0 + j) * BN + sBase) =
                make_float4(dpz[j][0], dpz[j][1], dpz[j][2], dpz[j][3]);
#pragma unroll
        for (int i = 0; i < 4; i++)
            *(float4*)(g_DT + (size_t)(sBase + i) * P2 + p0) =
                make_float4(dzp[0][i], dzp[1][i], dzp[2][i], dzp[3][i]);
    } else {
        // histogram + scan + scatter (overlaps tile mainloop)
        if (t < NC) s_cnt[t] = 0;
        __syncthreads();
        for (int j = t; j < BN; j += NTHR) atomicAdd(&s_cnt[g_yrel[j]], 1);
        __syncthreads();
        if (t == 0) {
            int acc = 0;
            for (int c = 0; c < NC; c++) { s_start[c] = acc; acc += s_cnt[c]; }
            s_start[NC] = acc;
        }
        __syncthreads();
        if (t < NC) { g_start[t] = s_start[t]; s_cur[t] = s_start[t]; }
        if (t == 0) g_start[NC] = s_start[NC];
        __syncthreads();
        for (int j = t; j < BN; j += NTHR) {
            int c = g_yrel[j];
            int pos = atomicAdd(&s_cur[c], 1);
            g_clsidx[pos] = j;
        }
    }

    grid_sync();   // D matrices + class lists ready

    // ---------------- Phase C: warp per anchor -------------------------------
    int gw = b * 12 + w;       // 0..1547
    for (int i = gw; i < NA; i += NWARPS_TOT) {
        int a = 3 * i;
        // nearest proxy: argmin over DT[a][*]
        float bv = INFINITY; int bp = 0x7fffffff;
        const float* dta = g_DT + (size_t)a * P2;
#pragma unroll
        for (int q = 0; q < 3; q++) {
            int p = lane + 32 * q;
            float d = (p < NP) ? dta[p] : INFINITY;
            if (d < bv || (d == bv && p < bp)) { bv = d; bp = p; }
        }
        warp_argmin(bv, bp);
        int px = bp;

        // hardest positive over masked class suffix
        int c = g_yrel[a];
        int lo = g_start[c], hi = g_start[c + 1];
        const float* Drow = g_Dpz + (size_t)px * BN;
        float hb = -INFINITY; int hj = 0x7fffffff;
        for (int idx = lo + lane; idx < hi; idx += 32) {
            int j = g_clsidx[idx];
            if (j >= a) {
                float d = Drow[j];
                if (d > hb || (d == hb && j < hj)) { hb = d; hj = j; }
            }
        }
        warp_argmax(hb, hj);

        // logsumexp over -DT[j_p][*]
        const float* dtj = g_DT + (size_t)hj * P2;
        float nd0 = (lane      < NP) ? -dtj[lane]      : -INFINITY;
        float nd1 = (lane + 32 < NP) ? -dtj[lane + 32] : -INFINITY;
        float nd2 = (lane + 64 < NP) ? -dtj[lane + 64] : -INFINITY;
        float m = fmaxf(nd0, fmaxf(nd1, nd2));
#pragma unroll
        for (int o = 16; o; o >>= 1) m = fmaxf(m, __shfl_xor_sync(0xffffffffu, m, o));
        float s = expf(nd0 - m) + expf(nd1 - m) + expf(nd2 - m);
        s = warp_sum(s);
        if (lane == 0) g_loss[i] = hb + (m + logf(s));
    }

    // ---------------- mean: last block -----------------------------------
    __threadfence();
    __syncthreads();
    if (t == 0) s_last = (atomicAdd(&g_done, 1u) == (unsigned)(gridDim.x - 1));
    __syncthreads();
    if (s_last) {
        __threadfence();
        float s = 0.f;
        for (int k = t; k < NA; k += NTHR) s += g_loss[k];
        s = warp_sum(s);
        if (lane == 0) rbuf[w] = s;
        __syncthreads();
        if (t == 0) {
            float total = 0.f;
#pragma unroll
            for (int q = 0; q < 12; q++) total += rbuf[q];
            out[0] = total / (float)NA;
            g_done = 0;
        }
    }
}

// ---------------- launch ------------------------------------------------------
extern "C" void kernel_launch(void* const* d_in, const int* in_sizes, int n_in,
                              void* d_out, int out_size) {
    const float* z       = (const float*)d_in[0];
    const int*   y_idx   = (const int*)d_in[1];
    const float* proxies = (const float*)d_in[2];
    const int*   y_map   = (const int*)d_in[3];
    float*       out     = (float*)d_out;

    k_all<<<NBLK, NTHR>>>(z, y_idx, y_map, proxies, out);
}

// round 7
// speedup vs baseline: 1.4130x; 1.4130x over previous
#include <cuda_runtime.h>
#include <cuda_bf16.h>
#include <math.h>

#define BN     8192
#define ZD     128
#define NC     62
#define NP     93
#define P2     96        // padded proxies
#define NA     2730      // anchors 0,3,...,8187
#define EPSV   1e-6f
#define EPS2T  1.28e-10f // ZD*EPS^2
#define SZP    132       // padded smem z row (floats)
#define DTHR   768       // k_dist threads
#define HB_W   8         // anchors (warps) per k_hard block
#define HGRID  ((NA + HB_W - 1) / HB_W)   // 342

#define SMEM_Z_FLOATS   (64 * SZP)            // 8448
#define SMEM_P_FLOATS   (ZD * P2)             // 12288
#define SMEM_DYN_BYTES  ((SMEM_Z_FLOATS + SMEM_P_FLOATS) * 4)   // 82944

// ---------------- persistent scratch (device globals, zero-init) -------------
__device__ int   g_yrel[BN];
__device__ int   g_start[NC + 1];
__device__ int   g_clsidx[BN];
__device__ float g_Dpz[P2 * BN];       // dist(proxy p, z j), eps sign psum-zs
__device__ float g_DT [BN * P2];       // dist(z j, proxy p), eps sign zs-psum
__device__ float g_loss[NA];
__device__ unsigned int g_done;

// ---------------- helpers ---------------------------------------------------
__device__ __forceinline__ float warp_sum(float v) {
#pragma unroll
    for (int o = 16; o; o >>= 1) v += __shfl_xor_sync(0xffffffffu, v, o);
    return v;
}
__device__ __forceinline__ void warp_argmin(float& v, int& i) {
#pragma unroll
    for (int o = 16; o; o >>= 1) {
        float v2 = __shfl_xor_sync(0xffffffffu, v, o);
        int   i2 = __shfl_xor_sync(0xffffffffu, i, o);
        if (v2 < v || (v2 == v && i2 < i)) { v = v2; i = i2; }
    }
}
__device__ __forceinline__ void warp_argmax(float& v, int& i) {
#pragma unroll
    for (int o = 16; o; o >>= 1) {
        float v2 = __shfl_xor_sync(0xffffffffu, v, o);
        int   i2 = __shfl_xor_sync(0xffffffffu, i, o);
        if (v2 > v || (v2 == v && i2 < i)) { v = v2; i = i2; }
    }
}

// ============ K1: dense distance matrix, self-contained ======================
// grid: 129 blocks x 768 threads. Blocks 0..127: 96x64 tile (proxies
// normalized per-block into dynamic shared). Block 128: y_rel + scatter.
__global__ void __launch_bounds__(DTHR) k_dist(const float* __restrict__ z,
                                               const int* __restrict__ y_idx,
                                               const int* __restrict__ y_map,
                                               const float* __restrict__ proxies) {
    extern __shared__ float smem[];
    float* s_z    = smem;                    // [64][SZP]
    float* s_prxT = smem + SMEM_Z_FLOATS;    // [ZD][P2]
    __shared__ float s_zz[64], s_zs[64];
    __shared__ float s_pss[P2], s_psum[P2];

    int b = blockIdx.x, t = threadIdx.x;
    int w = t >> 5, lane = t & 31;

    if (b == 128) {  // ---- service: y_rel + histogram + scan + scatter ----
        __shared__ int s_inv[NC];
        __shared__ int cnt[NC], cur[NC], start[NC + 1];
        if (t < NC) { s_inv[y_map[t]] = t; cnt[t] = 0; }
        __syncthreads();
        for (int j = t; j < BN; j += DTHR) {
            int r = s_inv[y_idx[j]];
            g_yrel[j] = r;
            atomicAdd(&cnt[r], 1);
        }
        __syncthreads();
        if (t == 0) {
            int acc = 0;
            for (int c = 0; c < NC; c++) { start[c] = acc; acc += cnt[c]; }
            start[NC] = acc;
        }
        __syncthreads();
        if (t < NC) { g_start[t] = start[t]; cur[t] = start[t]; }
        if (t == 0) g_start[NC] = start[NC];
        __syncthreads();
        for (int j = t; j < BN; j += DTHR) {
            int c = s_inv[y_idx[j]];
            int pos = atomicAdd(&cur[c], 1);
            g_clsidx[pos] = j;
        }
        return;
    }

    // ---- stage 64 z rows (warp-aligned stride -> free per-row stats) ----
    const float4* z4 = (const float4*)z;
    for (int idx = t; idx < 64 * 32; idx += DTHR) {
        int r = idx >> 5, q = idx & 31;      // r warp-uniform
        float4 v = z4[(size_t)(b * 64 + r) * 32 + q];
        float* dst = &s_z[r * SZP + 4 * q];
        dst[0] = v.x; dst[1] = v.y; dst[2] = v.z; dst[3] = v.w;
        float s  = (v.x + v.y) + (v.z + v.w);
        float ss = (v.x * v.x + v.y * v.y) + (v.z * v.z + v.w * v.w);
#pragma unroll
        for (int o = 16; o; o >>= 1) {
            s  += __shfl_xor_sync(0xffffffffu, s, o);
            ss += __shfl_xor_sync(0xffffffffu, ss, o);
        }
        if (lane == 0) { s_zs[r] = s; s_zz[r] = ss; }
    }
    // ---- normalize proxies into shared (warp per proxy row, 24 warps) ----
    for (int p = w; p < NP; p += 24) {
        float4 v = ((const float4*)(proxies + p * ZD))[lane];
        float ss = warp_sum(v.x * v.x + v.y * v.y + v.z * v.z + v.w * v.w);
        float inv = 1.f / fmaxf(sqrtf(ss), 1e-12f);
        float4 o = make_float4(v.x * inv, v.y * inv, v.z * inv, v.w * inv);
        int k0 = 4 * lane;
        s_prxT[(k0 + 0) * P2 + p] = o.x;
        s_prxT[(k0 + 1) * P2 + p] = o.y;
        s_prxT[(k0 + 2) * P2 + p] = o.z;
        s_prxT[(k0 + 3) * P2 + p] = o.w;
        float so  = warp_sum(o.x + o.y + o.z + o.w);
        float so2 = warp_sum(o.x * o.x + o.y * o.y + o.z * o.z + o.w * o.w);
        if (lane == 0) { s_psum[p] = so; s_pss[p] = so2; }
    }
    // zero pad columns 93..95 (all k) and pad stats
    for (int idx = t; idx < ZD * 3; idx += DTHR)
        s_prxT[(idx / 3) * P2 + NP + (idx % 3)] = 0.f;
    if (t >= NP && t < P2) { s_pss[t] = 0.f; s_psum[t] = 0.f; }
    __syncthreads();

    // ---- mainloop: thread tile 4 proxies x 2 samples ----
    int pg = t % 24, sg = t / 24;            // 24 proxy-groups x 32 sample-groups
    int p0 = 4 * pg, s0 = 2 * sg;
    const float4* prxT4 = (const float4*)s_prxT;

    float acc[4][2];
#pragma unroll
    for (int j = 0; j < 4; j++) { acc[j][0] = 0.f; acc[j][1] = 0.f; }

#pragma unroll 4
    for (int k = 0; k < ZD; k++) {
        float4 pv = prxT4[k * 24 + pg];
        float zv0 = s_z[(s0 + 0) * SZP + k];
        float zv1 = s_z[(s0 + 1) * SZP + k];
        acc[0][0] = fmaf(pv.x, zv0, acc[0][0]); acc[0][1] = fmaf(pv.x, zv1, acc[0][1]);
        acc[1][0] = fmaf(pv.y, zv0, acc[1][0]); acc[1][1] = fmaf(pv.y, zv1, acc[1][1]);
        acc[2][0] = fmaf(pv.z, zv0, acc[2][0]); acc[2][1] = fmaf(pv.z, zv1, acc[2][1]);
        acc[3][0] = fmaf(pv.w, zv0, acc[3][0]); acc[3][1] = fmaf(pv.w, zv1, acc[3][1]);
    }

    int sBase = b * 64 + s0;
    float pssv[4], psmv[4], zzv[2], zsv[2];
#pragma unroll
    for (int j = 0; j < 4; j++) { pssv[j] = s_pss[p0 + j]; psmv[j] = s_psum[p0 + j]; }
#pragma unroll
    for (int i = 0; i < 2; i++) { zzv[i] = s_zz[s0 + i]; zsv[i] = s_zs[s0 + i]; }

    float dpz[4][2], dzp[4][2];
#pragma unroll
    for (int j = 0; j < 4; j++)
#pragma unroll
        for (int i = 0; i < 2; i++) {
            float base = zzv[i] + pssv[j] - 2.f * acc[j][i];
            float e = 2.f * EPSV * (psmv[j] - zsv[i]);
            dpz[j][i] = sqrtf(fmaxf(base + e + EPS2T, 0.f));
            dzp[j][i] = sqrtf(fmaxf(base - e + EPS2T, 0.f));
        }

#pragma unroll
    for (int j = 0; j < 4; j++)      // Dpz rows: float2 over samples
        *(float2*)(g_Dpz + (size_t)(p0 + j) * BN + sBase) =
            make_float2(dpz[j][0], dpz[j][1]);
#pragma unroll
    for (int i = 0; i < 2; i++)      // DT rows: float4 over proxies
        *(float4*)(g_DT + (size_t)(sBase + i) * P2 + p0) =
            make_float4(dzp[0][i], dzp[1][i], dzp[2][i], dzp[3][i]);
}

// ============ K2: warp-per-anchor: nearest + hardpos + lse + mean ============
// grid: HGRID blocks x 256 threads
__global__ void __launch_bounds__(256) k_hard(float* __restrict__ out) {
    __shared__ float rbuf[8];
    __shared__ int s_last;
    int t = threadIdx.x, w = t >> 5, lane = t & 31;
    int i = blockIdx.x * HB_W + w;

    if (i < NA) {
        int a = 3 * i;
        // nearest proxy: argmin over DT[a][*]
        float bv = INFINITY; int bp = 0x7fffffff;
        const float* dta = g_DT + (size_t)a * P2;
#pragma unroll
        for (int q = 0; q < 3; q++) {
            int p = lane + 32 * q;
            float d = (p < NP) ? dta[p] : INFINITY;
            if (d < bv || (d == bv && p < bp)) { bv = d; bp = p; }
        }
        warp_argmin(bv, bp);
        int px = bp;

        // hardest positive over masked class suffix
        int c = g_yrel[a];
        int lo = g_start[c], hi = g_start[c + 1];
        const float* Drow = g_Dpz + (size_t)px * BN;
        float hb = -INFINITY; int hj = 0x7fffffff;
        for (int idx = lo + lane; idx < hi; idx += 32) {
            int j = g_clsidx[idx];
            if (j >= a) {
                float d = Drow[j];
                if (d > hb || (d == hb && j < hj)) { hb = d; hj = j; }
            }
        }
        warp_argmax(hb, hj);

        // logsumexp over -DT[j_p][*]
        const float* dtj = g_DT + (size_t)hj * P2;
        float nd0 = (lane      < NP) ? -dtj[lane]      : -INFINITY;
        float nd1 = (lane + 32 < NP) ? -dtj[lane + 32] : -INFINITY;
        float nd2 = (lane + 64 < NP) ? -dtj[lane + 64] : -INFINITY;
        float m = fmaxf(nd0, fmaxf(nd1, nd2));
#pragma unroll
        for (int o = 16; o; o >>= 1) m = fmaxf(m, __shfl_xor_sync(0xffffffffu, m, o));
        float s = expf(nd0 - m) + expf(nd1 - m) + expf(nd2 - m);
        s = warp_sum(s);
        if (lane == 0) g_loss[i] = hb + (m + logf(s));
    }

    // ---- last block computes deterministic mean ----
    __threadfence();
    __syncthreads();
    if (t == 0) s_last = (atomicAdd(&g_done, 1u) == (unsigned)(gridDim.x - 1));
    __syncthreads();
    if (s_last) {
        __threadfence();
        float s = 0.f;
        for (int k = t; k < NA; k += 256) s += g_loss[k];
        s = warp_sum(s);
        if (lane == 0) rbuf[w] = s;
        __syncthreads();
        if (t == 0) {
            float total = 0.f;
#pragma unroll
            for (int q = 0; q < 8; q++) total += rbuf[q];
            out[0] = total / (float)NA;
            g_done = 0;
        }
    }
}

// ---------------- launch ------------------------------------------------------
extern "C" void kernel_launch(void* const* d_in, const int* in_sizes, int n_in,
                              void* d_out, int out_size) {
    const float* z       = (const float*)d_in[0];
    const int*   y_idx   = (const int*)d_in[1];
    const float* proxies = (const float*)d_in[2];
    const int*   y_map   = (const int*)d_in[3];
    float*       out     = (float*)d_out;

    cudaFuncSetAttribute(k_dist, cudaFuncAttributeMaxDynamicSharedMemorySize,
                         SMEM_DYN_BYTES);
    k_dist<<<129, DTHR, SMEM_DYN_BYTES>>>(z, y_idx, y_map, proxies);
    k_hard<<<HGRID, 256>>>(out);
}